// round 1
// baseline (speedup 1.0000x reference)
#include <cuda_runtime.h>
#include <cuda_bf16.h>

#define BN 2
#define CIN 64
#define COUT 64
#define HH 256
#define WW 256
#define KK 9
#define OC1 10          // only offset channels 0..9 are ever needed
#define HW (HH*WW)

// ---------------- scratch (no allocations allowed) ----------------
__device__ float g_off[BN*OC1*HW];        // conv1 output, channels 0..9
__device__ float g_offstats[BN*5*2];      // mean,rstd for offset GN groups 0..4
__device__ float g_wp[576*64];            // repacked w_dsc: [r=k*64+ci][co]
__device__ float g_part[BN*1024*16*2];    // per-block partial (sum,sumsq) for out-GN
__device__ float g_outmr[BN*16*2];        // mean,rstd for out-GN groups

// ---------------- kernel 1: 3x3 conv, 64 -> 10 channels ----------------
__global__ void conv1_kernel(const float* __restrict__ x,
                             const float* __restrict__ w,
                             const float* __restrict__ bias) {
    int b = blockIdx.z, w0 = blockIdx.x * 32, h0 = blockIdx.y * 8;
    int t = threadIdx.x;
    int tw = t & 31, th = t >> 5;
    __shared__ float xs[10][34];
    __shared__ float ws[OC1][9];
    float acc[OC1];
#pragma unroll
    for (int o = 0; o < OC1; o++) acc[o] = 0.f;

    for (int ci = 0; ci < CIN; ci++) {
        for (int i = t; i < 340; i += 256) {
            int r = i / 34, c = i % 34;
            int hy = h0 - 1 + r, wx = w0 - 1 + c;
            float v = 0.f;
            if (hy >= 0 && hy < HH && wx >= 0 && wx < WW)
                v = x[((size_t)(b*CIN + ci)*HH + hy)*WW + wx];
            xs[r][c] = v;
        }
        if (t < OC1*9) ws[t/9][t%9] = w[(t/9)*CIN*9 + ci*9 + (t%9)];
        __syncthreads();

        float xv[9];
#pragma unroll
        for (int dy = 0; dy < 3; dy++)
#pragma unroll
            for (int dx = 0; dx < 3; dx++)
                xv[dy*3+dx] = xs[th+dy][tw+dx];
#pragma unroll
        for (int o = 0; o < OC1; o++) {
            float a = acc[o];
#pragma unroll
            for (int tp = 0; tp < 9; tp++) a = fmaf(ws[o][tp], xv[tp], a);
            acc[o] = a;
        }
        __syncthreads();
    }
#pragma unroll
    for (int o = 0; o < OC1; o++)
        g_off[((size_t)(b*OC1 + o)*HH + h0 + th)*WW + w0 + tw] = acc[o] + bias[o];
}

// ---------------- kernel 2: offset GN stats (groups of 2 channels) ----------------
__global__ void offstats_kernel() {
    int b = blockIdx.x / 5, g = blockIdx.x % 5;
    int t = threadIdx.x;
    const float* base = g_off + (size_t)(b*OC1 + 2*g)*HW;  // channels 2g,2g+1 contiguous
    float s = 0.f, q = 0.f;
    for (int i = t; i < 2*HW; i += 256) { float v = base[i]; s += v; q += v*v; }
    __shared__ float rs[256], rq[256];
    rs[t] = s; rq[t] = q; __syncthreads();
    for (int o = 128; o > 0; o >>= 1) {
        if (t < o) { rs[t] += rs[t+o]; rq[t] += rq[t+o]; }
        __syncthreads();
    }
    if (t == 0) {
        float n = (float)(2*HW);
        float mean = rs[0] / n;
        float var = rq[0] / n - mean*mean;
        g_offstats[(b*5+g)*2]   = mean;
        g_offstats[(b*5+g)*2+1] = rsqrtf(var + 1e-5f);
    }
}

// ---------------- kernel 3: repack w_dsc -> [r=k*64+ci][co] ----------------
__global__ void repack_kernel(const float* __restrict__ wdsc) {
    int lin = blockIdx.x*256 + threadIdx.x;
    if (lin < 576*64) {
        int co = lin & 63, r = lin >> 6;
        int ci = r & 63, k = r >> 6;
        g_wp[r*64 + co] = wdsc[((size_t)(co*64 + ci))*9 + k];
    }
}

// ---------------- kernel 4: fused coords + sampling + 64x576 GEMM + partial GN sums ----------------
// Block: one (b, h) row segment of 64 pixels. 256 threads.
__global__ void __launch_bounds__(256, 1)
main_kernel(const float* __restrict__ x,
            const float* __restrict__ gno_w, const float* __restrict__ gno_b,
            const float* __restrict__ b_dsc,
            float* __restrict__ out) {
    extern __shared__ float sm[];
    float* s_sh  = sm;                       // [576][64]
    float* w_sh  = sm + 36864;               // [32][64]
    float* wy_sh = sm + 36864 + 2048;        // [9][64]
    int*   y0_sh = (int*)(wy_sh + 576);      // [9][64]
    int*   y1_sh = y0_sh + 576;
    int*   xi_sh = y1_sh + 576;
    __shared__ float blk_sums[32];

    int t = threadIdx.x;
    int b = blockIdx.z, h = blockIdx.y, w0 = blockIdx.x * 64;
    if (t < 32) blk_sums[t] = 0.f;

    // Phase 0: GN+tanh on offsets, outward cumsum, coordinates (1 thread / pixel)
    if (t < 64) {
        int p = t, wg = w0 + p;
        float v[9];
#pragma unroll
        for (int c = 0; c < 9; c++) {
            float raw = g_off[((size_t)(b*OC1 + c)*HH + h)*WW + wg];
            int g = c >> 1;
            float mean = g_offstats[(b*5+g)*2];
            float rstd = g_offstats[(b*5+g)*2+1];
            v[c] = tanhf((raw - mean)*rstd*gno_w[c] + gno_b[c]);
        }
        float cum[9];
        cum[4] = 0.f;
        cum[3] = v[3]; cum[2] = cum[3]+v[2]; cum[1] = cum[2]+v[1]; cum[0] = cum[1]+v[0];
        cum[5] = v[5]; cum[6] = cum[5]+v[6]; cum[7] = cum[6]+v[7]; cum[8] = cum[7]+v[8];
#pragma unroll
        for (int k = 0; k < 9; k++) {
            float iy = (float)h + cum[k];
            iy = fminf(fmaxf(iy, 0.f), 255.f);
            float y0f = floorf(iy);
            int y0i = (int)y0f;
            int y1i = min(y0i + 1, 255);
            int ix  = min(max(wg + k - 4, 0), 255);   // x offsets are exact integers
            wy_sh[k*64+p] = iy - y0f;
            y0_sh[k*64+p] = y0i;
            y1_sh[k*64+p] = y1i;
            xi_sh[k*64+p] = ix;
        }
    }
    __syncthreads();

    // Phase 1: sampling (2-tap linear in y) -> s_sh[r=k*64+ci][pix]
    {
        int lane = t & 31, wq = t >> 5;
        for (int rr = wq; rr < 576; rr += 8) {
            int k = rr >> 6, ci = rr & 63;
            const float* base = x + (size_t)(b*CIN + ci)*HW;
#pragma unroll
            for (int pp = 0; pp < 2; pp++) {
                int p = lane + pp*32;
                int y0i = y0_sh[k*64+p], y1i = y1_sh[k*64+p], ix = xi_sh[k*64+p];
                float wy = wy_sh[k*64+p];
                float a = __ldg(base + y0i*WW + ix);
                float c = __ldg(base + y1i*WW + ix);
                s_sh[rr*64 + p] = a + (c - a)*wy;
            }
        }
    }
    __syncthreads();

    // Phase 2: GEMM  out[co][pix] += W[co][r] * s[r][pix], 4co x 4pix per thread
    int com = t & 15, pixm = t >> 4;
    float acc[4][4];
#pragma unroll
    for (int i = 0; i < 4; i++)
#pragma unroll
        for (int j = 0; j < 4; j++) acc[i][j] = 0.f;

    for (int rb = 0; rb < 576; rb += 32) {
        for (int i = t; i < 2048; i += 256) w_sh[i] = g_wp[rb*64 + i];
        __syncthreads();
#pragma unroll
        for (int j = 0; j < 32; j++) {
            float4 wv = *(const float4*)&w_sh[j*64 + com*4];
            float4 sv = *(const float4*)&s_sh[(rb + j)*64 + pixm*4];
            acc[0][0] = fmaf(wv.x, sv.x, acc[0][0]); acc[0][1] = fmaf(wv.x, sv.y, acc[0][1]);
            acc[0][2] = fmaf(wv.x, sv.z, acc[0][2]); acc[0][3] = fmaf(wv.x, sv.w, acc[0][3]);
            acc[1][0] = fmaf(wv.y, sv.x, acc[1][0]); acc[1][1] = fmaf(wv.y, sv.y, acc[1][1]);
            acc[1][2] = fmaf(wv.y, sv.z, acc[1][2]); acc[1][3] = fmaf(wv.y, sv.w, acc[1][3]);
            acc[2][0] = fmaf(wv.z, sv.x, acc[2][0]); acc[2][1] = fmaf(wv.z, sv.y, acc[2][1]);
            acc[2][2] = fmaf(wv.z, sv.z, acc[2][2]); acc[2][3] = fmaf(wv.z, sv.w, acc[2][3]);
            acc[3][0] = fmaf(wv.w, sv.x, acc[3][0]); acc[3][1] = fmaf(wv.w, sv.y, acc[3][1]);
            acc[3][2] = fmaf(wv.w, sv.z, acc[3][2]); acc[3][3] = fmaf(wv.w, sv.w, acc[3][3]);
        }
        __syncthreads();
    }

    // Epilogue: bias, store pre-GN output, accumulate group (sum,sumsq)
    float lsum = 0.f, lsq = 0.f;
    int co0 = com*4, p0 = pixm*4;
#pragma unroll
    for (int i = 0; i < 4; i++) {
        int co = co0 + i;
        float bia = b_dsc[co];
        float4 o;
        o.x = acc[i][0] + bia; o.y = acc[i][1] + bia;
        o.z = acc[i][2] + bia; o.w = acc[i][3] + bia;
        lsum += o.x + o.y + o.z + o.w;
        lsq  += o.x*o.x + o.y*o.y + o.z*o.z + o.w*o.w;
        *(float4*)&out[((size_t)(b*COUT + co)*HH + h)*WW + w0 + p0] = o;
    }
    // each thread's 4 co are exactly one GN group (g = com)
    atomicAdd(&blk_sums[com*2],   lsum);
    atomicAdd(&blk_sums[com*2+1], lsq);
    __syncthreads();
    if (t < 32) {
        int bw = blockIdx.x + 4*blockIdx.y;   // block index within this batch: 0..1023
        g_part[((size_t)(b*1024 + bw)*16 + (t >> 1))*2 + (t & 1)] = blk_sums[t];
    }
}

// ---------------- kernel 5: reduce out-GN partials ----------------
__global__ void outstats_kernel() {
    int b = blockIdx.x >> 4, g = blockIdx.x & 15;
    int t = threadIdx.x;
    float s = 0.f, q = 0.f;
    for (int i = t; i < 1024; i += 256) {
        size_t idx = ((size_t)(b*1024 + i)*16 + g)*2;
        s += g_part[idx];
        q += g_part[idx + 1];
    }
    __shared__ float rs[256], rq[256];
    rs[t] = s; rq[t] = q; __syncthreads();
    for (int o = 128; o > 0; o >>= 1) {
        if (t < o) { rs[t] += rs[t+o]; rq[t] += rq[t+o]; }
        __syncthreads();
    }
    if (t == 0) {
        float n = 4.f * HW;
        float mean = rs[0] / n;
        float var = rq[0] / n - mean*mean;
        g_outmr[(b*16+g)*2]   = mean;
        g_outmr[(b*16+g)*2+1] = rsqrtf(var + 1e-5f);
    }
}

// ---------------- kernel 6: apply GN + ReLU in place ----------------
__global__ void apply_kernel(float* __restrict__ out,
                             const float* __restrict__ gn_w,
                             const float* __restrict__ gn_b) {
    int idx4 = blockIdx.x*blockDim.x + threadIdx.x;   // 0..2097151
    size_t base = (size_t)idx4 * 4;
    int co = (int)((base >> 16) & 63);
    int b  = (int)(base >> 22);
    int g  = co >> 2;
    float mean = g_outmr[(b*16+g)*2];
    float rstd = g_outmr[(b*16+g)*2+1];
    float sc = rstd * gn_w[co];
    float sh = gn_b[co] - mean * sc;
    float4 v = *(float4*)&out[base];
    v.x = fmaxf(fmaf(v.x, sc, sh), 0.f);
    v.y = fmaxf(fmaf(v.y, sc, sh), 0.f);
    v.z = fmaxf(fmaf(v.z, sc, sh), 0.f);
    v.w = fmaxf(fmaf(v.w, sc, sh), 0.f);
    *(float4*)&out[base] = v;
}

// ---------------- launch ----------------
extern "C" void kernel_launch(void* const* d_in, const int* in_sizes, int n_in,
                              void* d_out, int out_size) {
    const float* x     = (const float*)d_in[0];
    const float* w_off = (const float*)d_in[1];
    const float* b_off = (const float*)d_in[2];
    const float* gno_w = (const float*)d_in[3];
    const float* gno_b = (const float*)d_in[4];
    const float* w_dsc = (const float*)d_in[5];
    const float* b_dsc = (const float*)d_in[6];
    const float* gn_w  = (const float*)d_in[7];
    const float* gn_b  = (const float*)d_in[8];
    float* out = (float*)d_out;

    const int smem_bytes = (36864 + 2048 + 576) * 4 + 576 * 3 * 4;  // 164864 B
    cudaFuncSetAttribute(main_kernel, cudaFuncAttributeMaxDynamicSharedMemorySize, smem_bytes);

    conv1_kernel<<<dim3(WW/32, HH/8, BN), 256>>>(x, w_off, b_off);
    offstats_kernel<<<BN*5, 256>>>();
    repack_kernel<<<(576*64 + 255)/256, 256>>>(w_dsc);
    main_kernel<<<dim3(4, HH, BN), 256, smem_bytes>>>(x, gno_w, gno_b, b_dsc, out);
    outstats_kernel<<<BN*16, 256>>>();
    apply_kernel<<<4096, 512>>>(out, gn_w, gn_b);
}

// round 2
// speedup vs baseline: 1.7067x; 1.7067x over previous
#include <cuda_runtime.h>
#include <cuda_bf16.h>

#define BN 2
#define CIN 64
#define COUT 64
#define HH 256
#define WW 256
#define KK 9
#define OC1 10          // only offset channels 0..9 are ever needed
#define HW (HH*WW)

// ---------------- scratch (no allocations allowed) ----------------
__device__ float g_off[BN*OC1*HW];        // conv1 output, channels 0..9
__device__ float g_offstats[BN*5*2];      // mean,rstd for offset GN groups 0..4
__device__ float g_wp[576*64];            // repacked w_dsc: [r=k*64+ci][co]
__device__ float g_part[BN*1024*16*2];    // per-block partial (sum,sumsq) for out-GN
__device__ float g_outmr[BN*16*2];        // mean,rstd for out-GN groups

// ---------------- kernel 1: 3x3 conv, 64 -> 10 channels ----------------
__global__ void conv1_kernel(const float* __restrict__ x,
                             const float* __restrict__ w,
                             const float* __restrict__ bias) {
    int b = blockIdx.z, w0 = blockIdx.x * 32, h0 = blockIdx.y * 8;
    int t = threadIdx.x;
    int tw = t & 31, th = t >> 5;
    __shared__ float xs[10][34];
    __shared__ float ws[OC1][9];
    float acc[OC1];
#pragma unroll
    for (int o = 0; o < OC1; o++) acc[o] = 0.f;

    for (int ci = 0; ci < CIN; ci++) {
        for (int i = t; i < 340; i += 256) {
            int r = i / 34, c = i % 34;
            int hy = h0 - 1 + r, wx = w0 - 1 + c;
            float v = 0.f;
            if (hy >= 0 && hy < HH && wx >= 0 && wx < WW)
                v = x[((size_t)(b*CIN + ci)*HH + hy)*WW + wx];
            xs[r][c] = v;
        }
        if (t < OC1*9) ws[t/9][t%9] = w[(t/9)*CIN*9 + ci*9 + (t%9)];
        __syncthreads();

        float xv[9];
#pragma unroll
        for (int dy = 0; dy < 3; dy++)
#pragma unroll
            for (int dx = 0; dx < 3; dx++)
                xv[dy*3+dx] = xs[th+dy][tw+dx];
#pragma unroll
        for (int o = 0; o < OC1; o++) {
            float a = acc[o];
#pragma unroll
            for (int tp = 0; tp < 9; tp++) a = fmaf(ws[o][tp], xv[tp], a);
            acc[o] = a;
        }
        __syncthreads();
    }
#pragma unroll
    for (int o = 0; o < OC1; o++)
        g_off[((size_t)(b*OC1 + o)*HH + h0 + th)*WW + w0 + tw] = acc[o] + bias[o];
}

// ---------------- kernel 2: offset GN stats (groups of 2 channels) ----------------
__global__ void offstats_kernel() {
    int b = blockIdx.x / 5, g = blockIdx.x % 5;
    int t = threadIdx.x;
    const float* base = g_off + (size_t)(b*OC1 + 2*g)*HW;
    float s = 0.f, q = 0.f;
    for (int i = t; i < 2*HW; i += 256) { float v = base[i]; s += v; q += v*v; }
    __shared__ float rs[256], rq[256];
    rs[t] = s; rq[t] = q; __syncthreads();
    for (int o = 128; o > 0; o >>= 1) {
        if (t < o) { rs[t] += rs[t+o]; rq[t] += rq[t+o]; }
        __syncthreads();
    }
    if (t == 0) {
        float n = (float)(2*HW);
        float mean = rs[0] / n;
        float var = rq[0] / n - mean*mean;
        g_offstats[(b*5+g)*2]   = mean;
        g_offstats[(b*5+g)*2+1] = rsqrtf(var + 1e-5f);
    }
}

// ---------------- kernel 3: repack w_dsc -> [r=k*64+ci][co] ----------------
__global__ void repack_kernel(const float* __restrict__ wdsc) {
    int lin = blockIdx.x*256 + threadIdx.x;
    if (lin < 576*64) {
        int co = lin & 63, r = lin >> 6;
        int ci = r & 63, k = r >> 6;
        g_wp[r*64 + co] = wdsc[((size_t)(co*64 + ci))*9 + k];
    }
}

// ---------------- kernel 4: fused coords + sampling + GEMM (k-chunked) ----------------
// Block: one (b, h) row segment of 64 pixels. 256 threads, 4 CTAs/SM.
__global__ void __launch_bounds__(256, 4)
main_kernel(const float* __restrict__ x,
            const float* __restrict__ gno_w, const float* __restrict__ gno_b,
            const float* __restrict__ b_dsc,
            float* __restrict__ out) {
    __shared__ float s_sh[64*64];    // [ci][pix] for current k
    __shared__ float w_sh[64*64];    // [ci][co]  for current k
    __shared__ float wy_sh[576];
    __shared__ int   y0_sh[576];
    __shared__ int   y1_sh[576];
    __shared__ int   xi_sh[576];
    __shared__ float blk_sums[32];

    int t = threadIdx.x;
    int b = blockIdx.z, h = blockIdx.y, w0 = blockIdx.x * 64;
    if (t < 32) blk_sums[t] = 0.f;

    // Phase 0: GN+tanh on offsets, outward cumsum, coordinates for all 9 taps
    if (t < 64) {
        int p = t, wg = w0 + p;
        float v[9];
#pragma unroll
        for (int c = 0; c < 9; c++) {
            float raw = g_off[((size_t)(b*OC1 + c)*HH + h)*WW + wg];
            int g = c >> 1;
            float mean = g_offstats[(b*5+g)*2];
            float rstd = g_offstats[(b*5+g)*2+1];
            v[c] = tanhf((raw - mean)*rstd*gno_w[c] + gno_b[c]);
        }
        float cum[9];
        cum[4] = 0.f;
        cum[3] = v[3]; cum[2] = cum[3]+v[2]; cum[1] = cum[2]+v[1]; cum[0] = cum[1]+v[0];
        cum[5] = v[5]; cum[6] = cum[5]+v[6]; cum[7] = cum[6]+v[7]; cum[8] = cum[7]+v[8];
#pragma unroll
        for (int k = 0; k < 9; k++) {
            float iy = (float)h + cum[k];
            iy = fminf(fmaxf(iy, 0.f), 255.f);
            float y0f = floorf(iy);
            int y0i = (int)y0f;
            int y1i = min(y0i + 1, 255);
            int ix  = min(max(wg + k - 4, 0), 255);   // x offsets are exact integers
            wy_sh[k*64+p] = iy - y0f;
            y0_sh[k*64+p] = y0i;
            y1_sh[k*64+p] = y1i;
            xi_sh[k*64+p] = ix;
        }
    }

    int com = t & 15, pixm = t >> 4;
    int lane = t & 31, wq = t >> 5;
    float acc[4][4];
#pragma unroll
    for (int i = 0; i < 4; i++)
#pragma unroll
        for (int j = 0; j < 4; j++) acc[i][j] = 0.f;

    const float* xb = x + (size_t)b*CIN*HW;

    for (int k = 0; k < KK; k++) {
        __syncthreads();   // previous FMA phase done reading s_sh/w_sh (and phase-0 coords ready)

        // load weight chunk: rows r = k*64 .. k*64+63
        for (int i = t; i < 4096; i += 256)
            w_sh[i] = g_wp[k*4096 + i];

        // sample s chunk: s_sh[ci*64 + p] (2-tap linear in y)
        for (int ci = wq; ci < 64; ci += 8) {
            const float* base = xb + (size_t)ci*HW;
#pragma unroll
            for (int pp = 0; pp < 2; pp++) {
                int p = lane + pp*32;
                int y0i = y0_sh[k*64+p], y1i = y1_sh[k*64+p], ix = xi_sh[k*64+p];
                float wy = wy_sh[k*64+p];
                float a = __ldg(base + y0i*WW + ix);
                float c = __ldg(base + y1i*WW + ix);
                s_sh[ci*64 + p] = a + (c - a)*wy;
            }
        }
        __syncthreads();

#pragma unroll 8
        for (int j = 0; j < 64; j++) {
            float4 wv = *(const float4*)&w_sh[j*64 + com*4];
            float4 sv = *(const float4*)&s_sh[j*64 + pixm*4];
            acc[0][0] = fmaf(wv.x, sv.x, acc[0][0]); acc[0][1] = fmaf(wv.x, sv.y, acc[0][1]);
            acc[0][2] = fmaf(wv.x, sv.z, acc[0][2]); acc[0][3] = fmaf(wv.x, sv.w, acc[0][3]);
            acc[1][0] = fmaf(wv.y, sv.x, acc[1][0]); acc[1][1] = fmaf(wv.y, sv.y, acc[1][1]);
            acc[1][2] = fmaf(wv.y, sv.z, acc[1][2]); acc[1][3] = fmaf(wv.y, sv.w, acc[1][3]);
            acc[2][0] = fmaf(wv.z, sv.x, acc[2][0]); acc[2][1] = fmaf(wv.z, sv.y, acc[2][1]);
            acc[2][2] = fmaf(wv.z, sv.z, acc[2][2]); acc[2][3] = fmaf(wv.z, sv.w, acc[2][3]);
            acc[3][0] = fmaf(wv.w, sv.x, acc[3][0]); acc[3][1] = fmaf(wv.w, sv.y, acc[3][1]);
            acc[3][2] = fmaf(wv.w, sv.z, acc[3][2]); acc[3][3] = fmaf(wv.w, sv.w, acc[3][3]);
        }
    }

    // Epilogue: bias, store pre-GN output, accumulate group (sum,sumsq)
    float lsum = 0.f, lsq = 0.f;
    int co0 = com*4, p0 = pixm*4;
#pragma unroll
    for (int i = 0; i < 4; i++) {
        int co = co0 + i;
        float bia = b_dsc[co];
        float4 o;
        o.x = acc[i][0] + bia; o.y = acc[i][1] + bia;
        o.z = acc[i][2] + bia; o.w = acc[i][3] + bia;
        lsum += o.x + o.y + o.z + o.w;
        lsq  += o.x*o.x + o.y*o.y + o.z*o.z + o.w*o.w;
        *(float4*)&out[((size_t)(b*COUT + co)*HH + h)*WW + w0 + p0] = o;
    }
    // each thread's 4 co are exactly one GN group (g = com)
    atomicAdd(&blk_sums[com*2],   lsum);
    atomicAdd(&blk_sums[com*2+1], lsq);
    __syncthreads();
    if (t < 32) {
        int bw = blockIdx.x + 4*blockIdx.y;   // block index within this batch: 0..1023
        g_part[((size_t)(b*1024 + bw)*16 + (t >> 1))*2 + (t & 1)] = blk_sums[t];
    }
}

// ---------------- kernel 5: reduce out-GN partials ----------------
__global__ void outstats_kernel() {
    int b = blockIdx.x >> 4, g = blockIdx.x & 15;
    int t = threadIdx.x;
    float s = 0.f, q = 0.f;
    for (int i = t; i < 1024; i += 256) {
        size_t idx = ((size_t)(b*1024 + i)*16 + g)*2;
        s += g_part[idx];
        q += g_part[idx + 1];
    }
    __shared__ float rs[256], rq[256];
    rs[t] = s; rq[t] = q; __syncthreads();
    for (int o = 128; o > 0; o >>= 1) {
        if (t < o) { rs[t] += rs[t+o]; rq[t] += rq[t+o]; }
        __syncthreads();
    }
    if (t == 0) {
        float n = 4.f * HW;
        float mean = rs[0] / n;
        float var = rq[0] / n - mean*mean;
        g_outmr[(b*16+g)*2]   = mean;
        g_outmr[(b*16+g)*2+1] = rsqrtf(var + 1e-5f);
    }
}

// ---------------- kernel 6: apply GN + ReLU in place ----------------
__global__ void apply_kernel(float* __restrict__ out,
                             const float* __restrict__ gn_w,
                             const float* __restrict__ gn_b) {
    int idx4 = blockIdx.x*blockDim.x + threadIdx.x;   // 0..2097151
    size_t base = (size_t)idx4 * 4;
    int co = (int)((base >> 16) & 63);
    int b  = (int)(base >> 22);
    int g  = co >> 2;
    float mean = g_outmr[(b*16+g)*2];
    float rstd = g_outmr[(b*16+g)*2+1];
    float sc = rstd * gn_w[co];
    float sh = gn_b[co] - mean * sc;
    float4 v = *(float4*)&out[base];
    v.x = fmaxf(fmaf(v.x, sc, sh), 0.f);
    v.y = fmaxf(fmaf(v.y, sc, sh), 0.f);
    v.z = fmaxf(fmaf(v.z, sc, sh), 0.f);
    v.w = fmaxf(fmaf(v.w, sc, sh), 0.f);
    *(float4*)&out[base] = v;
}

// ---------------- launch ----------------
extern "C" void kernel_launch(void* const* d_in, const int* in_sizes, int n_in,
                              void* d_out, int out_size) {
    const float* x     = (const float*)d_in[0];
    const float* w_off = (const float*)d_in[1];
    const float* b_off = (const float*)d_in[2];
    const float* gno_w = (const float*)d_in[3];
    const float* gno_b = (const float*)d_in[4];
    const float* w_dsc = (const float*)d_in[5];
    const float* b_dsc = (const float*)d_in[6];
    const float* gn_w  = (const float*)d_in[7];
    const float* gn_b  = (const float*)d_in[8];
    float* out = (float*)d_out;

    conv1_kernel<<<dim3(WW/32, HH/8, BN), 256>>>(x, w_off, b_off);
    offstats_kernel<<<BN*5, 256>>>();
    repack_kernel<<<(576*64 + 255)/256, 256>>>(w_dsc);
    main_kernel<<<dim3(4, HH, BN), 256>>>(x, gno_w, gno_b, b_dsc, out);
    outstats_kernel<<<BN*16, 256>>>();
    apply_kernel<<<4096, 512>>>(out, gn_w, gn_b);
}

// round 4
// speedup vs baseline: 2.9596x; 1.7341x over previous
#include <cuda_runtime.h>
#include <cuda_bf16.h>
#include <cstdint>
#include <cstring>

#define BN 2
#define CIN 64
#define HH 256
#define WW 256
#define KK 9
#define OC1 10
#define HW (HH*WW)

// ---------------- scratch ----------------
__device__ float g_off[BN*OC1*HW];
__device__ float g_offstats[BN*5*2];
__device__ __align__(16) __nv_bfloat16 g_wbf[2*KK*4096];  // [split][k][swizzled 64co x 64ci]
__device__ float g_part[BN*512*16*2];
__device__ float g_outmr[BN*16*2];

// ---------------- mma helpers (baseline PTX, no 'a' features) ----------------
__device__ __forceinline__ uint32_t smem_u32(const void* p) {
    uint32_t a;
    asm("{ .reg .u64 t; cvta.to.shared.u64 t, %1; cvt.u32.u64 %0, t; }" : "=r"(a) : "l"(p));
    return a;
}
__device__ __forceinline__ void ldsm_x4(uint32_t* r, uint32_t addr) {
    asm volatile("ldmatrix.sync.aligned.m8n8.x4.shared.b16 {%0,%1,%2,%3}, [%4];"
                 : "=r"(r[0]), "=r"(r[1]), "=r"(r[2]), "=r"(r[3]) : "r"(addr));
}
__device__ __forceinline__ void ldsm_x2(uint32_t* r, uint32_t addr) {
    asm volatile("ldmatrix.sync.aligned.m8n8.x2.shared.b16 {%0,%1}, [%2];"
                 : "=r"(r[0]), "=r"(r[1]) : "r"(addr));
}
__device__ __forceinline__ void mma16816(float* d, const uint32_t* a, const uint32_t* b) {
    asm volatile("mma.sync.aligned.m16n8k16.row.col.f32.bf16.bf16.f32 "
                 "{%0,%1,%2,%3}, {%4,%5,%6,%7}, {%8,%9}, {%0,%1,%2,%3};"
                 : "+f"(d[0]), "+f"(d[1]), "+f"(d[2]), "+f"(d[3])
                 : "r"(a[0]), "r"(a[1]), "r"(a[2]), "r"(a[3]), "r"(b[0]), "r"(b[1]));
}

// smem layout (dynamic)
#define OFF_SHI  0           // [128 pix][64 ci] bf16, 128B rows, swizzled (16 KB)
#define OFF_SLO  16384
#define OFF_WHI  32768       // [64 co][64 ci] bf16, 128B rows, swizzled (8 KB)
#define OFF_WLO  40960
#define OFF_IY   49152       // 9*128 floats (4608 B)
#define OFF_SUMS 53760       // 32 floats
#define SMEM_BYTES 53888

// ---------------- kernel 1: 3x3 conv, 64 -> 10 channels ----------------
__global__ void conv1_kernel(const float* __restrict__ x,
                             const float* __restrict__ w,
                             const float* __restrict__ bias) {
    int b = blockIdx.z, w0 = blockIdx.x * 32, h0 = blockIdx.y * 8;
    int t = threadIdx.x;
    int tw = t & 31, th = t >> 5;
    __shared__ float xs[10][34];
    __shared__ float ws[OC1][9];
    float acc[OC1];
#pragma unroll
    for (int o = 0; o < OC1; o++) acc[o] = 0.f;

    for (int ci = 0; ci < CIN; ci++) {
        for (int i = t; i < 340; i += 256) {
            int r = i / 34, c = i % 34;
            int hy = h0 - 1 + r, wx = w0 - 1 + c;
            float v = 0.f;
            if (hy >= 0 && hy < HH && wx >= 0 && wx < WW)
                v = x[((size_t)(b*CIN + ci)*HH + hy)*WW + wx];
            xs[r][c] = v;
        }
        if (t < OC1*9) ws[t/9][t%9] = w[(t/9)*CIN*9 + ci*9 + (t%9)];
        __syncthreads();

        float xv[9];
#pragma unroll
        for (int dy = 0; dy < 3; dy++)
#pragma unroll
            for (int dx = 0; dx < 3; dx++)
                xv[dy*3+dx] = xs[th+dy][tw+dx];
#pragma unroll
        for (int o = 0; o < OC1; o++) {
            float a = acc[o];
#pragma unroll
            for (int tp = 0; tp < 9; tp++) a = fmaf(ws[o][tp], xv[tp], a);
            acc[o] = a;
        }
        __syncthreads();
    }
#pragma unroll
    for (int o = 0; o < OC1; o++)
        g_off[((size_t)(b*OC1 + o)*HH + h0 + th)*WW + w0 + tw] = acc[o] + bias[o];
}

// ---------------- kernel 2: offset GN stats ----------------
__global__ void offstats_kernel() {
    int b = blockIdx.x / 5, g = blockIdx.x % 5;
    int t = threadIdx.x;
    const float* base = g_off + (size_t)(b*OC1 + 2*g)*HW;
    float s = 0.f, q = 0.f;
    for (int i = t; i < 2*HW; i += 256) { float v = base[i]; s += v; q += v*v; }
    __shared__ float rs[256], rq[256];
    rs[t] = s; rq[t] = q; __syncthreads();
    for (int o = 128; o > 0; o >>= 1) {
        if (t < o) { rs[t] += rs[t+o]; rq[t] += rq[t+o]; }
        __syncthreads();
    }
    if (t == 0) {
        float n = (float)(2*HW);
        float mean = rs[0] / n;
        float var = rq[0] / n - mean*mean;
        g_offstats[(b*5+g)*2]   = mean;
        g_offstats[(b*5+g)*2+1] = rsqrtf(var + 1e-5f);
    }
}

// ---------------- kernel 3: split w_dsc into bf16 hi/lo, [k][co][ci] swizzled ----------------
__global__ void wprep_kernel(const float* __restrict__ wdsc) {
    int lin = blockIdx.x*256 + threadIdx.x;       // 9*64*64
    if (lin >= KK*64*64) return;
    int ci = lin & 63, co = (lin >> 6) & 63, k = lin >> 12;
    float v = wdsc[((size_t)(co*64 + ci))*KK + k];
    __nv_bfloat16 hi = __float2bfloat16(v);
    __nv_bfloat16 lo = __float2bfloat16(v - __bfloat162float(hi));
    uint32_t off = (uint32_t)(co*128 + ci*2);
    uint32_t sw = off ^ ((off >> 3) & 0x70);
    *(__nv_bfloat16*)((char*)g_wbf + (size_t)k*8192 + sw) = hi;
    *(__nv_bfloat16*)((char*)g_wbf + (size_t)(KK + k)*8192 + sw) = lo;
}

// ---------------- kernel 4: fused coords + sampling + mma.sync GEMM ----------------
// CTA: 128 pixels (N) x 64 co (M), K = 9 taps x 64 ci. 256 threads, 3 CTAs/SM.
__global__ void __launch_bounds__(256, 3)
main_kernel(const float* __restrict__ x,
            const float* __restrict__ gno_w, const float* __restrict__ gno_b,
            const float* __restrict__ b_dsc,
            float* __restrict__ out) {
    extern __shared__ __align__(16) char smem[];
    uint32_t sb = smem_u32(smem);
    float* iy_sh = (float*)(smem + OFF_IY);
    float* sums  = (float*)(smem + OFF_SUMS);

    int t = threadIdx.x, lane = t & 31, wid = t >> 5;
    int b = blockIdx.z, h = blockIdx.y, w0 = blockIdx.x * 128;
    if (t < 32) sums[t] = 0.f;

    // Phase 0: GN+tanh, outward cumsum, clamped iy for 128 pixels x 9 taps
    if (t < 128) {
        int p = t, wg = w0 + p;
        float v[9];
#pragma unroll
        for (int c = 0; c < 9; c++) {
            float raw = g_off[((size_t)(b*OC1 + c)*HH + h)*WW + wg];
            int g = c >> 1;
            float mean = g_offstats[(b*5+g)*2];
            float rstd = g_offstats[(b*5+g)*2+1];
            v[c] = tanhf((raw - mean)*rstd*gno_w[c] + gno_b[c]);
        }
        float cum[9];
        cum[4] = 0.f;
        cum[3] = v[3]; cum[2] = cum[3]+v[2]; cum[1] = cum[2]+v[1]; cum[0] = cum[1]+v[0];
        cum[5] = v[5]; cum[6] = cum[5]+v[6]; cum[7] = cum[6]+v[7]; cum[8] = cum[7]+v[8];
#pragma unroll
        for (int k = 0; k < 9; k++)
            iy_sh[k*128 + p] = fminf(fmaxf((float)h + cum[k], 0.f), 255.f);
    }

    const float* xb = x + (size_t)b*CIN*HW;
    int pixw = (wid & 3)*32 + lane;      // sampling: pixel this thread owns
    int ci0base = (wid >> 2)*32;         // sampling: ci chunk

    // mma warp tiling: wm in {0,1} -> 32 co, wn in {0..3} -> 32 pix
    int wm = wid & 1, wn = wid >> 1;
    float acc[2][4][4];
#pragma unroll
    for (int i = 0; i < 2; i++)
#pragma unroll
        for (int j = 0; j < 4; j++)
#pragma unroll
            for (int l = 0; l < 4; l++) acc[i][j][l] = 0.f;

    for (int k = 0; k < KK; k++) {
        __syncthreads();   // previous mma phase done reading S/W

        // ---- sampling: S[pix][ci] bf16 hi/lo, swizzled 128B rows ----
        float iy = iy_sh[k*128 + pixw];
        float y0f = floorf(iy);
        float wy = iy - y0f;
        int y0 = (int)y0f;
        int y1 = min(y0 + 1, 255);
        int ix = min(max(w0 + pixw + k - 4, 0), 255);
        const float* p0 = xb + y0*WW + ix;
        const float* p1 = xb + y1*WW + ix;

#pragma unroll
        for (int g = 0; g < 4; g++) {
            int ci0 = ci0base + g*8;
            float v[8];
#pragma unroll
            for (int j = 0; j < 8; j++) {
                size_t o = (size_t)(ci0 + j)*HW;
                float a = __ldg(p0 + o), c = __ldg(p1 + o);
                v[j] = fmaf(c - a, wy, a);
            }
            uint32_t hp[4], lp[4];
#pragma unroll
            for (int j = 0; j < 4; j++) {
                __nv_bfloat162 h2 = __floats2bfloat162_rn(v[2*j], v[2*j+1]);
                float2 hf = __bfloat1622float2(h2);
                __nv_bfloat162 l2 = __floats2bfloat162_rn(v[2*j] - hf.x, v[2*j+1] - hf.y);
                memcpy(&hp[j], &h2, 4);
                memcpy(&lp[j], &l2, 4);
            }
            uint32_t off = (uint32_t)(pixw*128 + ci0*2);
            uint32_t sw = off ^ ((off >> 3) & 0x70);
            *(uint4*)(smem + OFF_SHI + sw) = make_uint4(hp[0], hp[1], hp[2], hp[3]);
            *(uint4*)(smem + OFF_SLO + sw) = make_uint4(lp[0], lp[1], lp[2], lp[3]);
        }

        // ---- copy this tap's weight tiles (pre-swizzled) ----
        {
            const uint4* whsrc = (const uint4*)((const char*)g_wbf + (size_t)k*8192);
            const uint4* wlsrc = (const uint4*)((const char*)g_wbf + (size_t)(KK + k)*8192);
            uint4* whd = (uint4*)(smem + OFF_WHI);
            uint4* wld = (uint4*)(smem + OFF_WLO);
            for (int i = t; i < 512; i += 256) { whd[i] = whsrc[i]; wld[i] = wlsrc[i]; }
        }
        __syncthreads();

        // ---- mma phase: 4 ksteps of 16 ci ----
#pragma unroll
        for (int kt = 0; kt < 4; kt++) {
            uint32_t ahi[2][4], alo[2][4];
#pragma unroll
            for (int mt = 0; mt < 2; mt++) {
                uint32_t row = (uint32_t)(wm*32 + mt*16 + (lane & 15));
                uint32_t c16 = (uint32_t)(kt*2 + (lane >> 4));
                uint32_t off = row*128 + c16*16;
                uint32_t sw = off ^ ((off >> 3) & 0x70);
                ldsm_x4(ahi[mt], sb + OFF_WHI + sw);
                ldsm_x4(alo[mt], sb + OFF_WLO + sw);
            }
            uint32_t bhi[4][2], blo[4][2];
#pragma unroll
            for (int nt = 0; nt < 4; nt++) {
                uint32_t row = (uint32_t)(wn*32 + nt*8 + (lane & 7));
                uint32_t c16 = (uint32_t)(kt*2 + ((lane >> 3) & 1));
                uint32_t off = row*128 + c16*16;
                uint32_t sw = off ^ ((off >> 3) & 0x70);
                ldsm_x2(bhi[nt], sb + OFF_SHI + sw);
                ldsm_x2(blo[nt], sb + OFF_SLO + sw);
            }
#pragma unroll
            for (int mt = 0; mt < 2; mt++)
#pragma unroll
                for (int nt = 0; nt < 4; nt++) {
                    mma16816(acc[mt][nt], ahi[mt], bhi[nt]);
                    mma16816(acc[mt][nt], alo[mt], bhi[nt]);
                    mma16816(acc[mt][nt], ahi[mt], blo[nt]);
                }
        }
    }

    // ---- epilogue: bias, store, GN partial sums ----
    {
        int q = lane >> 2;                    // co row within tile
        int pp = (lane & 3) * 2;              // pixel pair
        float s_l[2][2] = {{0.f,0.f},{0.f,0.f}}, q_l[2][2] = {{0.f,0.f},{0.f,0.f}};
#pragma unroll
        for (int mt = 0; mt < 2; mt++) {
            int cog = wm*32 + mt*16 + q;
            float b0 = __ldg(b_dsc + cog);
            float b1 = __ldg(b_dsc + cog + 8);
#pragma unroll
            for (int nt = 0; nt < 4; nt++) {
                int pix = wn*32 + nt*8 + pp;
                float v0 = acc[mt][nt][0] + b0;
                float v1 = acc[mt][nt][1] + b0;
                float v2 = acc[mt][nt][2] + b1;
                float v3 = acc[mt][nt][3] + b1;
                *(float2*)&out[((size_t)(b*64 + cog)*HH + h)*WW + w0 + pix]     = make_float2(v0, v1);
                *(float2*)&out[((size_t)(b*64 + cog + 8)*HH + h)*WW + w0 + pix] = make_float2(v2, v3);
                s_l[mt][0] += v0 + v1; q_l[mt][0] += v0*v0 + v1*v1;
                s_l[mt][1] += v2 + v3; q_l[mt][1] += v2*v2 + v3*v3;
            }
        }
        // reduce over pixel quads (lanes sharing q)
#pragma unroll
        for (int mt = 0; mt < 2; mt++)
#pragma unroll
            for (int hf = 0; hf < 2; hf++) {
#pragma unroll
                for (int m = 1; m <= 2; m <<= 1) {
                    s_l[mt][hf] += __shfl_xor_sync(0xffffffff, s_l[mt][hf], m);
                    q_l[mt][hf] += __shfl_xor_sync(0xffffffff, q_l[mt][hf], m);
                }
                if ((lane & 3) == 0) {
                    int grp = (wm*32 + mt*16 + hf*8 + q) >> 2;
                    atomicAdd(&sums[2*grp],   s_l[mt][hf]);
                    atomicAdd(&sums[2*grp+1], q_l[mt][hf]);
                }
            }
    }
    __syncthreads();
    if (t < 32) {
        int bw = blockIdx.x + 2*h;     // 0..511 within batch
        g_part[((size_t)(b*512 + bw)*16 + (t >> 1))*2 + (t & 1)] = sums[t];
    }
}

// ---------------- kernel 5: reduce out-GN partials ----------------
__global__ void outstats_kernel() {
    int b = blockIdx.x >> 4, g = blockIdx.x & 15;
    int t = threadIdx.x;
    float s = 0.f, q = 0.f;
    for (int i = t; i < 512; i += 256) {
        size_t idx = ((size_t)(b*512 + i)*16 + g)*2;
        s += g_part[idx];
        q += g_part[idx + 1];
    }
    __shared__ float rs[256], rq[256];
    rs[t] = s; rq[t] = q; __syncthreads();
    for (int o = 128; o > 0; o >>= 1) {
        if (t < o) { rs[t] += rs[t+o]; rq[t] += rq[t+o]; }
        __syncthreads();
    }
    if (t == 0) {
        float n = 4.f * HW;
        float mean = rs[0] / n;
        float var = rq[0] / n - mean*mean;
        g_outmr[(b*16+g)*2]   = mean;
        g_outmr[(b*16+g)*2+1] = rsqrtf(var + 1e-5f);
    }
}

// ---------------- kernel 6: apply GN + ReLU ----------------
__global__ void apply_kernel(float* __restrict__ out,
                             const float* __restrict__ gn_w,
                             const float* __restrict__ gn_b) {
    int idx4 = blockIdx.x*blockDim.x + threadIdx.x;
    size_t base = (size_t)idx4 * 4;
    int co = (int)((base >> 16) & 63);
    int b  = (int)(base >> 22);
    int g  = co >> 2;
    float mean = g_outmr[(b*16+g)*2];
    float rstd = g_outmr[(b*16+g)*2+1];
    float sc = rstd * gn_w[co];
    float sh = gn_b[co] - mean * sc;
    float4 v = *(float4*)&out[base];
    v.x = fmaxf(fmaf(v.x, sc, sh), 0.f);
    v.y = fmaxf(fmaf(v.y, sc, sh), 0.f);
    v.z = fmaxf(fmaf(v.z, sc, sh), 0.f);
    v.w = fmaxf(fmaf(v.w, sc, sh), 0.f);
    *(float4*)&out[base] = v;
}

// ---------------- launch ----------------
extern "C" void kernel_launch(void* const* d_in, const int* in_sizes, int n_in,
                              void* d_out, int out_size) {
    const float* x     = (const float*)d_in[0];
    const float* w_off = (const float*)d_in[1];
    const float* b_off = (const float*)d_in[2];
    const float* gno_w = (const float*)d_in[3];
    const float* gno_b = (const float*)d_in[4];
    const float* w_dsc = (const float*)d_in[5];
    const float* b_dsc = (const float*)d_in[6];
    const float* gn_w  = (const float*)d_in[7];
    const float* gn_b  = (const float*)d_in[8];
    float* out = (float*)d_out;

    cudaFuncSetAttribute(main_kernel, cudaFuncAttributeMaxDynamicSharedMemorySize, SMEM_BYTES);

    conv1_kernel<<<dim3(WW/32, HH/8, BN), 256>>>(x, w_off, b_off);
    offstats_kernel<<<BN*5, 256>>>();
    wprep_kernel<<<(KK*64*64 + 255)/256, 256>>>(w_dsc);
    main_kernel<<<dim3(2, HH, BN), 256, SMEM_BYTES>>>(x, gno_w, gno_b, b_dsc, out);
    outstats_kernel<<<BN*16, 256>>>();
    apply_kernel<<<4096, 512>>>(out, gn_w, gn_b);
}

// round 5
// speedup vs baseline: 3.0337x; 1.0250x over previous
#include <cuda_runtime.h>
#include <cuda_bf16.h>
#include <cstdint>
#include <cstring>

#define BN 2
#define CIN 64
#define HH 256
#define WW 256
#define KK 9
#define OC1 10
#define HW (HH*WW)

// ---------------- scratch ----------------
__device__ float g_off[BN*OC1*HW];
__device__ float g_offpart[BN*256*20];    // per-conv1-block (sum,sumsq) x 10 ch
__device__ float g_offstats[BN*5*2];
__device__ __align__(16) __nv_bfloat16 g_wbf[2*KK*4096];  // [split][k][swizzled 64co x 64ci]
__device__ float g_part[BN*512*16*2];
__device__ float g_outmr[BN*16*2];

// ---------------- mma helpers (baseline PTX, no 'a' features) ----------------
__device__ __forceinline__ uint32_t smem_u32(const void* p) {
    uint32_t a;
    asm("{ .reg .u64 t; cvta.to.shared.u64 t, %1; cvt.u32.u64 %0, t; }" : "=r"(a) : "l"(p));
    return a;
}
__device__ __forceinline__ void ldsm_x4(uint32_t* r, uint32_t addr) {
    asm volatile("ldmatrix.sync.aligned.m8n8.x4.shared.b16 {%0,%1,%2,%3}, [%4];"
                 : "=r"(r[0]), "=r"(r[1]), "=r"(r[2]), "=r"(r[3]) : "r"(addr));
}
__device__ __forceinline__ void ldsm_x2(uint32_t* r, uint32_t addr) {
    asm volatile("ldmatrix.sync.aligned.m8n8.x2.shared.b16 {%0,%1}, [%2];"
                 : "=r"(r[0]), "=r"(r[1]) : "r"(addr));
}
__device__ __forceinline__ void mma16816(float* d, const uint32_t* a, const uint32_t* b) {
    asm volatile("mma.sync.aligned.m16n8k16.row.col.f32.bf16.bf16.f32 "
                 "{%0,%1,%2,%3}, {%4,%5,%6,%7}, {%8,%9}, {%0,%1,%2,%3};"
                 : "+f"(d[0]), "+f"(d[1]), "+f"(d[2]), "+f"(d[3])
                 : "r"(a[0]), "r"(a[1]), "r"(a[2]), "r"(a[3]), "r"(b[0]), "r"(b[1]));
}

// smem layout (dynamic), 2 stages
#define OFF_SHI(st)  ((st)*16384)            // [128 pix][64 ci] bf16 swizzled
#define OFF_SLO(st)  (32768 + (st)*16384)
#define OFF_WHI(st)  (65536 + (st)*8192)     // [64 co][64 ci] bf16 swizzled
#define OFF_WLO(st)  (81920 + (st)*8192)
#define OFF_IY   98304                        // 9*128 floats
#define OFF_SUMS 102912                       // 32 floats
#define SMEM_BYTES 103040

// ---------------- kernel 1: 3x3 conv, 64 -> 10 channels (+ GN stat partials) ----------------
__global__ void conv1_kernel(const float* __restrict__ x,
                             const float* __restrict__ w,
                             const float* __restrict__ bias) {
    int b = blockIdx.z, w0 = blockIdx.x * 32, h0 = blockIdx.y * 8;
    int t = threadIdx.x;
    int tw = t & 31, th = t >> 5;
    __shared__ float xs[10][34];
    __shared__ float ws[OC1][9];
    __shared__ float red[8][20];
    float acc[OC1];
#pragma unroll
    for (int o = 0; o < OC1; o++) acc[o] = 0.f;

    for (int ci = 0; ci < CIN; ci++) {
        for (int i = t; i < 340; i += 256) {
            int r = i / 34, c = i % 34;
            int hy = h0 - 1 + r, wx = w0 - 1 + c;
            float v = 0.f;
            if (hy >= 0 && hy < HH && wx >= 0 && wx < WW)
                v = x[((size_t)(b*CIN + ci)*HH + hy)*WW + wx];
            xs[r][c] = v;
        }
        if (t < OC1*9) ws[t/9][t%9] = w[(t/9)*CIN*9 + ci*9 + (t%9)];
        __syncthreads();

        float xv[9];
#pragma unroll
        for (int dy = 0; dy < 3; dy++)
#pragma unroll
            for (int dx = 0; dx < 3; dx++)
                xv[dy*3+dx] = xs[th+dy][tw+dx];
#pragma unroll
        for (int o = 0; o < OC1; o++) {
            float a = acc[o];
#pragma unroll
            for (int tp = 0; tp < 9; tp++) a = fmaf(ws[o][tp], xv[tp], a);
            acc[o] = a;
        }
        __syncthreads();
    }
    int lane = t & 31, wid = t >> 5;
#pragma unroll
    for (int o = 0; o < OC1; o++) {
        float v = acc[o] + bias[o];
        g_off[((size_t)(b*OC1 + o)*HH + h0 + th)*WW + w0 + tw] = v;
        float s = v, q = v*v;
#pragma unroll
        for (int m = 16; m; m >>= 1) {
            s += __shfl_xor_sync(0xffffffff, s, m);
            q += __shfl_xor_sync(0xffffffff, q, m);
        }
        if (lane == 0) { red[wid][o*2] = s; red[wid][o*2+1] = q; }
    }
    __syncthreads();
    if (t < 20) {
        float a = 0.f;
#pragma unroll
        for (int wq = 0; wq < 8; wq++) a += red[wq][t];
        int blk = blockIdx.x + 8*blockIdx.y;   // 0..255
        g_offpart[((size_t)(b*256) + blk)*20 + t] = a;
    }
}

// ---------------- kernel 2: reduce offset GN partials ----------------
__global__ void offstats_kernel() {
    int b = blockIdx.x / 5, g = blockIdx.x % 5;
    int t = threadIdx.x;
    float s = 0.f, q = 0.f;
    for (int i = t; i < 256; i += 256) {
        const float* p = g_offpart + ((size_t)(b*256) + i)*20;
        s += p[(2*g)*2]   + p[(2*g+1)*2];
        q += p[(2*g)*2+1] + p[(2*g+1)*2+1];
    }
    __shared__ float rs[256], rq[256];
    rs[t] = s; rq[t] = q; __syncthreads();
    for (int o = 128; o > 0; o >>= 1) {
        if (t < o) { rs[t] += rs[t+o]; rq[t] += rq[t+o]; }
        __syncthreads();
    }
    if (t == 0) {
        float n = (float)(2*HW);
        float mean = rs[0] / n;
        float var = rq[0] / n - mean*mean;
        g_offstats[(b*5+g)*2]   = mean;
        g_offstats[(b*5+g)*2+1] = rsqrtf(var + 1e-5f);
    }
}

// ---------------- kernel 3: split w_dsc into bf16 hi/lo, [k][co][ci] swizzled ----------------
__global__ void wprep_kernel(const float* __restrict__ wdsc) {
    int lin = blockIdx.x*256 + threadIdx.x;       // 9*64*64
    if (lin >= KK*64*64) return;
    int ci = lin & 63, co = (lin >> 6) & 63, k = lin >> 12;
    float v = wdsc[((size_t)(co*64 + ci))*KK + k];
    __nv_bfloat16 hi = __float2bfloat16(v);
    __nv_bfloat16 lo = __float2bfloat16(v - __bfloat162float(hi));
    uint32_t off = (uint32_t)(co*128 + ci*2);
    uint32_t sw = off ^ ((off >> 3) & 0x70);
    *(__nv_bfloat16*)((char*)g_wbf + (size_t)k*8192 + sw) = hi;
    *(__nv_bfloat16*)((char*)g_wbf + (size_t)(KK + k)*8192 + sw) = lo;
}

// ---------------- kernel 4: fused coords + sampling + mma.sync GEMM (pipelined) ----------------
// CTA: 128 pixels (N) x 64 co (M), K = 9 taps x 64 ci. 256 threads, 2 CTAs/SM.
__global__ void __launch_bounds__(256, 2)
main_kernel(const float* __restrict__ x,
            const float* __restrict__ gno_w, const float* __restrict__ gno_b,
            const float* __restrict__ b_dsc,
            float* __restrict__ out) {
    extern __shared__ __align__(16) char smem[];
    uint32_t sb = smem_u32(smem);
    float* iy_sh = (float*)(smem + OFF_IY);
    float* sums  = (float*)(smem + OFF_SUMS);

    int t = threadIdx.x, lane = t & 31, wid = t >> 5;
    int b = blockIdx.z, h = blockIdx.y, w0 = blockIdx.x * 128;
    if (t < 32) sums[t] = 0.f;

    // Phase 0: GN+tanh, outward cumsum, clamped iy for 128 pixels x 9 taps
    if (t < 128) {
        int p = t, wg = w0 + p;
        float v[9];
#pragma unroll
        for (int c = 0; c < 9; c++) {
            float raw = g_off[((size_t)(b*OC1 + c)*HH + h)*WW + wg];
            int g = c >> 1;
            float mean = g_offstats[(b*5+g)*2];
            float rstd = g_offstats[(b*5+g)*2+1];
            v[c] = tanhf((raw - mean)*rstd*gno_w[c] + gno_b[c]);
        }
        float cum[9];
        cum[4] = 0.f;
        cum[3] = v[3]; cum[2] = cum[3]+v[2]; cum[1] = cum[2]+v[1]; cum[0] = cum[1]+v[0];
        cum[5] = v[5]; cum[6] = cum[5]+v[6]; cum[7] = cum[6]+v[7]; cum[8] = cum[7]+v[8];
#pragma unroll
        for (int k = 0; k < 9; k++)
            iy_sh[k*128 + p] = fminf(fmaxf((float)h + cum[k], 0.f), 255.f);
    }
    __syncthreads();

    const float* xb = x + (size_t)b*CIN*HW;
    int pixw = (wid & 3)*32 + lane;      // sampling: pixel this thread owns
    int ci0base = (wid >> 2)*32;         // sampling: ci chunk base

    // mma warp tiling: wm in {0,1} -> 32 co, wn in {0..3} -> 32 pix
    int wm = wid & 1, wn = wid >> 1;
    float acc[2][4][4];
#pragma unroll
    for (int i = 0; i < 2; i++)
#pragma unroll
        for (int j = 0; j < 4; j++)
#pragma unroll
            for (int l = 0; l < 4; l++) acc[i][j][l] = 0.f;

    // ---- prologue: sample tap 0 + W0 into stage 0 ----
    {
        float iy = iy_sh[pixw];
        float y0f = floorf(iy);
        float wy = iy - y0f;
        int y0 = (int)y0f, y1 = min(y0 + 1, 255);
        int ix = min(max(w0 + pixw - 4, 0), 255);
        const float* p0 = xb + y0*WW + ix;
        const float* p1 = xb + y1*WW + ix;
#pragma unroll
        for (int g = 0; g < 4; g++) {
            int ci0 = ci0base + g*8;
            float v[8];
#pragma unroll
            for (int j = 0; j < 8; j++) {
                size_t o = (size_t)(ci0 + j)*HW;
                float a = __ldg(p0 + o), c = __ldg(p1 + o);
                v[j] = fmaf(c - a, wy, a);
            }
            uint32_t hp[4], lp[4];
#pragma unroll
            for (int j = 0; j < 4; j++) {
                __nv_bfloat162 h2 = __floats2bfloat162_rn(v[2*j], v[2*j+1]);
                float2 hf = __bfloat1622float2(h2);
                __nv_bfloat162 l2 = __floats2bfloat162_rn(v[2*j] - hf.x, v[2*j+1] - hf.y);
                memcpy(&hp[j], &h2, 4);
                memcpy(&lp[j], &l2, 4);
            }
            uint32_t off = (uint32_t)(pixw*128 + ci0*2);
            uint32_t sw = off ^ ((off >> 3) & 0x70);
            *(uint4*)(smem + OFF_SHI(0) + sw) = make_uint4(hp[0], hp[1], hp[2], hp[3]);
            *(uint4*)(smem + OFF_SLO(0) + sw) = make_uint4(lp[0], lp[1], lp[2], lp[3]);
        }
        const uint4* whsrc = (const uint4*)((const char*)g_wbf);
        const uint4* wlsrc = (const uint4*)((const char*)g_wbf + (size_t)KK*8192);
        uint4* whd = (uint4*)(smem + OFF_WHI(0));
        uint4* wld = (uint4*)(smem + OFF_WLO(0));
        whd[t] = whsrc[t]; whd[t+256] = whsrc[t+256];
        wld[t] = wlsrc[t]; wld[t+256] = wlsrc[t+256];
    }
    __syncthreads();

    // ---- main loop: mma tap k (stage k&1) interleaved with sampling tap k+1 ----
    for (int k = 0; k < KK; k++) {
        int st = k & 1, ns = st ^ 1;
        bool pf = (k < KK-1);

        float wy = 0.f;
        const float *p0 = xb, *p1 = xb;
        uint4 wh0, wh1, wl0, wl1;
        if (pf) {
            float iy = iy_sh[(k+1)*128 + pixw];
            float y0f = floorf(iy);
            wy = iy - y0f;
            int y0 = (int)y0f, y1 = min(y0 + 1, 255);
            int ix = min(max(w0 + pixw + (k+1) - 4, 0), 255);
            p0 = xb + y0*WW + ix;
            p1 = xb + y1*WW + ix;
            const uint4* whsrc = (const uint4*)((const char*)g_wbf + (size_t)(k+1)*8192);
            const uint4* wlsrc = (const uint4*)((const char*)g_wbf + (size_t)(KK+k+1)*8192);
            wh0 = whsrc[t]; wh1 = whsrc[t+256];
            wl0 = wlsrc[t]; wl1 = wlsrc[t+256];
        }

        uint32_t shib = sb + OFF_SHI(st), slob = sb + OFF_SLO(st);
        uint32_t whib = sb + OFF_WHI(st), wlob = sb + OFF_WLO(st);

#pragma unroll
        for (int g = 0; g < 4; g++) {
            // issue gather LDGs for tap k+1, chunk g (consumed after the mma kstep)
            float v[8];
            if (pf) {
                int ci0 = ci0base + g*8;
#pragma unroll
                for (int j = 0; j < 8; j++) {
                    size_t o = (size_t)(ci0 + j)*HW;
                    float a = __ldg(p0 + o), c = __ldg(p1 + o);
                    v[j] = fmaf(c - a, wy, a);
                }
            }

            // mma kstep g on stage st
            {
                int kt = g;
                uint32_t ahi[2][4], alo[2][4];
#pragma unroll
                for (int mt = 0; mt < 2; mt++) {
                    uint32_t row = (uint32_t)(wm*32 + mt*16 + (lane & 15));
                    uint32_t c16 = (uint32_t)(kt*2 + (lane >> 4));
                    uint32_t off = row*128 + c16*16;
                    uint32_t sw = off ^ ((off >> 3) & 0x70);
                    ldsm_x4(ahi[mt], whib + sw);
                    ldsm_x4(alo[mt], wlob + sw);
                }
                uint32_t bhi[4][2], blo[4][2];
#pragma unroll
                for (int nt = 0; nt < 4; nt++) {
                    uint32_t row = (uint32_t)(wn*32 + nt*8 + (lane & 7));
                    uint32_t c16 = (uint32_t)(kt*2 + ((lane >> 3) & 1));
                    uint32_t off = row*128 + c16*16;
                    uint32_t sw = off ^ ((off >> 3) & 0x70);
                    ldsm_x2(bhi[nt], shib + sw);
                    ldsm_x2(blo[nt], slob + sw);
                }
#pragma unroll
                for (int mt = 0; mt < 2; mt++)
#pragma unroll
                    for (int nt = 0; nt < 4; nt++) {
                        mma16816(acc[mt][nt], ahi[mt], bhi[nt]);
                        mma16816(acc[mt][nt], alo[mt], bhi[nt]);
                        mma16816(acc[mt][nt], ahi[mt], blo[nt]);
                    }
            }

            // convert + store tap k+1 chunk g into stage ns
            if (pf) {
                int ci0 = ci0base + g*8;
                uint32_t hp[4], lp[4];
#pragma unroll
                for (int j = 0; j < 4; j++) {
                    __nv_bfloat162 h2 = __floats2bfloat162_rn(v[2*j], v[2*j+1]);
                    float2 hf = __bfloat1622float2(h2);
                    __nv_bfloat162 l2 = __floats2bfloat162_rn(v[2*j] - hf.x, v[2*j+1] - hf.y);
                    memcpy(&hp[j], &h2, 4);
                    memcpy(&lp[j], &l2, 4);
                }
                uint32_t off = (uint32_t)(pixw*128 + ci0*2);
                uint32_t sw = off ^ ((off >> 3) & 0x70);
                *(uint4*)(smem + OFF_SHI(ns) + sw) = make_uint4(hp[0], hp[1], hp[2], hp[3]);
                *(uint4*)(smem + OFF_SLO(ns) + sw) = make_uint4(lp[0], lp[1], lp[2], lp[3]);
            }
        }

        if (pf) {
            uint4* whd = (uint4*)(smem + OFF_WHI(ns));
            uint4* wld = (uint4*)(smem + OFF_WLO(ns));
            whd[t] = wh0; whd[t+256] = wh1;
            wld[t] = wl0; wld[t+256] = wl1;
        }
        __syncthreads();
    }

    // ---- epilogue: bias, store, GN partial sums ----
    {
        int q = lane >> 2;                    // co row within tile
        int pp = (lane & 3) * 2;              // pixel pair
        float s_l[2][2] = {{0.f,0.f},{0.f,0.f}}, q_l[2][2] = {{0.f,0.f},{0.f,0.f}};
#pragma unroll
        for (int mt = 0; mt < 2; mt++) {
            int cog = wm*32 + mt*16 + q;
            float b0 = __ldg(b_dsc + cog);
            float b1 = __ldg(b_dsc + cog + 8);
#pragma unroll
            for (int nt = 0; nt < 4; nt++) {
                int pix = wn*32 + nt*8 + pp;
                float v0 = acc[mt][nt][0] + b0;
                float v1 = acc[mt][nt][1] + b0;
                float v2 = acc[mt][nt][2] + b1;
                float v3 = acc[mt][nt][3] + b1;
                *(float2*)&out[((size_t)(b*64 + cog)*HH + h)*WW + w0 + pix]     = make_float2(v0, v1);
                *(float2*)&out[((size_t)(b*64 + cog + 8)*HH + h)*WW + w0 + pix] = make_float2(v2, v3);
                s_l[mt][0] += v0 + v1; q_l[mt][0] += v0*v0 + v1*v1;
                s_l[mt][1] += v2 + v3; q_l[mt][1] += v2*v2 + v3*v3;
            }
        }
#pragma unroll
        for (int mt = 0; mt < 2; mt++)
#pragma unroll
            for (int hf = 0; hf < 2; hf++) {
#pragma unroll
                for (int m = 1; m <= 2; m <<= 1) {
                    s_l[mt][hf] += __shfl_xor_sync(0xffffffff, s_l[mt][hf], m);
                    q_l[mt][hf] += __shfl_xor_sync(0xffffffff, q_l[mt][hf], m);
                }
                if ((lane & 3) == 0) {
                    int grp = (wm*32 + mt*16 + hf*8 + q) >> 2;
                    atomicAdd(&sums[2*grp],   s_l[mt][hf]);
                    atomicAdd(&sums[2*grp+1], q_l[mt][hf]);
                }
            }
    }
    __syncthreads();
    if (t < 32) {
        int bw = blockIdx.x + 2*h;     // 0..511 within batch
        g_part[((size_t)(b*512 + bw)*16 + (t >> 1))*2 + (t & 1)] = sums[t];
    }
}

// ---------------- kernel 5: reduce out-GN partials ----------------
__global__ void outstats_kernel() {
    int b = blockIdx.x >> 4, g = blockIdx.x & 15;
    int t = threadIdx.x;
    float s = 0.f, q = 0.f;
    for (int i = t; i < 512; i += 256) {
        size_t idx = ((size_t)(b*512 + i)*16 + g)*2;
        s += g_part[idx];
        q += g_part[idx + 1];
    }
    __shared__ float rs[256], rq[256];
    rs[t] = s; rq[t] = q; __syncthreads();
    for (int o = 128; o > 0; o >>= 1) {
        if (t < o) { rs[t] += rs[t+o]; rq[t] += rq[t+o]; }
        __syncthreads();
    }
    if (t == 0) {
        float n = 4.f * HW;
        float mean = rs[0] / n;
        float var = rq[0] / n - mean*mean;
        g_outmr[(b*16+g)*2]   = mean;
        g_outmr[(b*16+g)*2+1] = rsqrtf(var + 1e-5f);
    }
}

// ---------------- kernel 6: apply GN + ReLU ----------------
__global__ void apply_kernel(float* __restrict__ out,
                             const float* __restrict__ gn_w,
                             const float* __restrict__ gn_b) {
    int idx4 = blockIdx.x*blockDim.x + threadIdx.x;
    size_t base = (size_t)idx4 * 4;
    int co = (int)((base >> 16) & 63);
    int b  = (int)(base >> 22);
    int g  = co >> 2;
    float mean = g_outmr[(b*16+g)*2];
    float rstd = g_outmr[(b*16+g)*2+1];
    float sc = rstd * gn_w[co];
    float sh = gn_b[co] - mean * sc;
    float4 v = *(float4*)&out[base];
    v.x = fmaxf(fmaf(v.x, sc, sh), 0.f);
    v.y = fmaxf(fmaf(v.y, sc, sh), 0.f);
    v.z = fmaxf(fmaf(v.z, sc, sh), 0.f);
    v.w = fmaxf(fmaf(v.w, sc, sh), 0.f);
    *(float4*)&out[base] = v;
}

// ---------------- launch ----------------
extern "C" void kernel_launch(void* const* d_in, const int* in_sizes, int n_in,
                              void* d_out, int out_size) {
    const float* x     = (const float*)d_in[0];
    const float* w_off = (const float*)d_in[1];
    const float* b_off = (const float*)d_in[2];
    const float* gno_w = (const float*)d_in[3];
    const float* gno_b = (const float*)d_in[4];
    const float* w_dsc = (const float*)d_in[5];
    const float* b_dsc = (const float*)d_in[6];
    const float* gn_w  = (const float*)d_in[7];
    const float* gn_b  = (const float*)d_in[8];
    float* out = (float*)d_out;

    cudaFuncSetAttribute(main_kernel, cudaFuncAttributeMaxDynamicSharedMemorySize, SMEM_BYTES);

    conv1_kernel<<<dim3(WW/32, HH/8, BN), 256>>>(x, w_off, b_off);
    offstats_kernel<<<BN*5, 256>>>();
    wprep_kernel<<<(KK*64*64 + 255)/256, 256>>>(w_dsc);
    main_kernel<<<dim3(2, HH, BN), 256, SMEM_BYTES>>>(x, gno_w, gno_b, b_dsc, out);
    outstats_kernel<<<BN*16, 256>>>();
    apply_kernel<<<4096, 512>>>(out, gn_w, gn_b);
}